// round 12
// baseline (speedup 1.0000x reference)
#include <cuda_runtime.h>
#include <cuda_fp16.h>

// CompetitiveLayer: 21 x { AF = AT/(1+K@BF); BF = BT/(1+AF@K) }, K = param^2,
// then C = param^2 * AF[:,None] * BF[None,:].
//
// Structure (R11 post-mortem): iter_kernel reads the fp16 K exactly ONCE per
// iteration (~3us, at the L2 floor) — each block owns 8 rows, computes AF for
// them, stages the 8x4096 fp16 tile in smem, then produces column partials.
// R11's failure was the 512-way partial reduction (26us latency-bound).
// Fix: partials are accumulated with DETERMINISTIC fixed-point u64 atomics
// (integer add is exactly associative -> bitwise reproducible, no fences),
// and a trivial bf_fin kernel divides + resets the accumulator (which also
// restores the zero invariant for graph replays).

#define N        4096
#define NITER    21
#define R        8                 // rows per iteration block
#define NBLK_IT  (N / R)           // 512 blocks
#define NTHR     256

#define FIXSCALE 1048576.0f        // 2^20
#define FIXINV   (1.0f / 1048576.0f)

// smem layout: sBF (fp32, 16KB) | tile (fp16, 64KB) | sAFloc (8 floats)
#define SMEM_IT  (N * 4 + R * N * 2 + 64)

// Scratch — __device__ globals (no cudaMalloc allowed)
__device__ __half g_Kh[(size_t)N * N];      // fp16 param^2 (32 MB)
__device__ float  g_AF[N];
__device__ float  g_BF[N];
__device__ unsigned long long g_acc[N];     // fixed-point column sums; zero at
                                            // entry, restored to zero by bf_fin

// ---------------------------------------------------------------------------
// Per-iteration kernel. Block b owns rows [8b, 8b+8).
//   pass 1 (warp per row): AF[i] = AT[i]/(1 + Kh[i,:].BF); tile row -> smem.
//           first==1: read P fp32, square, convert; also persist to g_Kh.
//   pass 2 (thread per 16 cols): g_acc[j] += llrint(2^20 * sum_r AF[r]*tile[r][j])
// No cross-block sync, no fences. K touched once per iteration.
// ---------------------------------------------------------------------------
__global__ __launch_bounds__(NTHR)
void iter_kernel(const float* __restrict__ P,
                 const float* __restrict__ AT,
                 const float* __restrict__ BT,
                 int first)
{
    extern __shared__ __align__(16) char smem_raw[];
    float*  sBF    = reinterpret_cast<float*>(smem_raw);                 // [N]
    __half* tile   = reinterpret_cast<__half*>(smem_raw + N * 4);        // [R*N]
    float*  sAFloc = reinterpret_cast<float*>(smem_raw + N * 4 + R * N * 2);

    const int tid  = threadIdx.x;
    const int bid  = blockIdx.x;
    const int warp = tid >> 5;
    const int lane = tid & 31;

    // ---- stage BF (fp32) into smem ----
    {
        const float4* src = first ? reinterpret_cast<const float4*>(BT)
                                  : reinterpret_cast<const float4*>(g_BF);
        float4* dst = reinterpret_cast<float4*>(sBF);
        #pragma unroll
        for (int i = tid; i < N / 4; i += NTHR) dst[i] = src[i];
    }
    __syncthreads();

    // ---- pass 1: one row per warp ----
    const int row = bid * R + warp;
    uint4* krow_s = reinterpret_cast<uint4*>(tile + warp * N);
    float acc = 0.f;

    if (first) {
        const float4* prow = reinterpret_cast<const float4*>(P + ((size_t)row << 12));
        uint4* krow_g = reinterpret_cast<uint4*>(g_Kh + ((size_t)row << 12));
        #pragma unroll
        for (int j = lane; j < N / 8; j += 32) {          // 16 trips
            float4 a = prow[2 * j];
            float4 b = prow[2 * j + 1];
            float s0 = a.x * a.x, s1 = a.y * a.y, s2 = a.z * a.z, s3 = a.w * a.w;
            float s4 = b.x * b.x, s5 = b.y * b.y, s6 = b.z * b.z, s7 = b.w * b.w;
            const float* bf = &sBF[j * 8];
            acc = fmaf(s0, bf[0], acc); acc = fmaf(s1, bf[1], acc);
            acc = fmaf(s2, bf[2], acc); acc = fmaf(s3, bf[3], acc);
            acc = fmaf(s4, bf[4], acc); acc = fmaf(s5, bf[5], acc);
            acc = fmaf(s6, bf[6], acc); acc = fmaf(s7, bf[7], acc);
            __half2 h0 = __floats2half2_rn(s0, s1);
            __half2 h1 = __floats2half2_rn(s2, s3);
            __half2 h2 = __floats2half2_rn(s4, s5);
            __half2 h3 = __floats2half2_rn(s6, s7);
            uint4 v;
            v.x = *reinterpret_cast<unsigned*>(&h0);
            v.y = *reinterpret_cast<unsigned*>(&h1);
            v.z = *reinterpret_cast<unsigned*>(&h2);
            v.w = *reinterpret_cast<unsigned*>(&h3);
            krow_s[j] = v;
            __stcg(&krow_g[j], v);    // persist fp16 K for later iterations
        }
    } else {
        const uint4* krow_g = reinterpret_cast<const uint4*>(g_Kh + ((size_t)row << 12));
        #pragma unroll
        for (int j = lane; j < N / 8; j += 32) {          // 16 trips, 16B each
            uint4 v = krow_g[j];
            krow_s[j] = v;
            const float* bf = &sBF[j * 8];
            float2 f0 = __half22float2(*reinterpret_cast<__half2*>(&v.x));
            float2 f1 = __half22float2(*reinterpret_cast<__half2*>(&v.y));
            float2 f2 = __half22float2(*reinterpret_cast<__half2*>(&v.z));
            float2 f3 = __half22float2(*reinterpret_cast<__half2*>(&v.w));
            acc = fmaf(f0.x, bf[0], acc); acc = fmaf(f0.y, bf[1], acc);
            acc = fmaf(f1.x, bf[2], acc); acc = fmaf(f1.y, bf[3], acc);
            acc = fmaf(f2.x, bf[4], acc); acc = fmaf(f2.y, bf[5], acc);
            acc = fmaf(f3.x, bf[6], acc); acc = fmaf(f3.y, bf[7], acc);
        }
    }
    #pragma unroll
    for (int o = 16; o > 0; o >>= 1) acc += __shfl_xor_sync(0xFFFFFFFFu, acc, o);
    if (lane == 0) {
        float af = AT[row] / (1.0f + acc);
        sAFloc[warp] = af;
        __stcg(&g_AF[row], af);       // for later iterations / final C
    }
    __syncthreads();

    // ---- pass 2: column partials from smem tile; thread owns 16 cols ----
    {
        const int j0 = tid * 16;                           // column index
        float accc[16];
        #pragma unroll
        for (int k = 0; k < 16; k++) accc[k] = 0.f;

        #pragma unroll
        for (int r = 0; r < R; r++) {                      // fixed order
            const float a = sAFloc[r];
            uint4 v0 = *reinterpret_cast<const uint4*>(tile + r * N + j0);
            uint4 v1 = *reinterpret_cast<const uint4*>(tile + r * N + j0 + 8);
            float2 f;
            f = __half22float2(*reinterpret_cast<__half2*>(&v0.x));
            accc[0]  = fmaf(a, f.x, accc[0]);  accc[1]  = fmaf(a, f.y, accc[1]);
            f = __half22float2(*reinterpret_cast<__half2*>(&v0.y));
            accc[2]  = fmaf(a, f.x, accc[2]);  accc[3]  = fmaf(a, f.y, accc[3]);
            f = __half22float2(*reinterpret_cast<__half2*>(&v0.z));
            accc[4]  = fmaf(a, f.x, accc[4]);  accc[5]  = fmaf(a, f.y, accc[5]);
            f = __half22float2(*reinterpret_cast<__half2*>(&v0.w));
            accc[6]  = fmaf(a, f.x, accc[6]);  accc[7]  = fmaf(a, f.y, accc[7]);
            f = __half22float2(*reinterpret_cast<__half2*>(&v1.x));
            accc[8]  = fmaf(a, f.x, accc[8]);  accc[9]  = fmaf(a, f.y, accc[9]);
            f = __half22float2(*reinterpret_cast<__half2*>(&v1.y));
            accc[10] = fmaf(a, f.x, accc[10]); accc[11] = fmaf(a, f.y, accc[11]);
            f = __half22float2(*reinterpret_cast<__half2*>(&v1.z));
            accc[12] = fmaf(a, f.x, accc[12]); accc[13] = fmaf(a, f.y, accc[13]);
            f = __half22float2(*reinterpret_cast<__half2*>(&v1.w));
            accc[14] = fmaf(a, f.x, accc[14]); accc[15] = fmaf(a, f.y, accc[15]);
        }

        // Deterministic fixed-point accumulation: integer adds commute exactly.
        // accc[k] in [0, 8) -> scaled < 2^23; 512 blocks -> total < 2^32 << u64.
        #pragma unroll
        for (int k = 0; k < 16; k++) {
            unsigned long long q =
                (unsigned long long)llrintf(accc[k] * FIXSCALE);
            atomicAdd(&g_acc[j0 + k], q);
        }
    }
}

// ---------------------------------------------------------------------------
// bf_fin: BF[j] = BT[j] / (1 + acc[j] * 2^-20); reset acc[j] = 0.
// The reset restores the zero invariant for the next iteration AND for the
// next graph replay (acc is statically zero-initialized).
// grid = 16 x 256.
// ---------------------------------------------------------------------------
__global__ __launch_bounds__(256, 4)
void bf_fin_kernel(const float* __restrict__ BT)
{
    const int j = blockIdx.x * 256 + threadIdx.x;
    unsigned long long v = g_acc[j];
    g_acc[j] = 0ULL;
    float s = (float)v * FIXINV;
    g_BF[j] = BT[j] / (1.0f + s);
}

// ---------------------------------------------------------------------------
// Output: C[i][j] = param[i][j]^2 * AF[i] * BF[j]  — exact fp32 K.
// ---------------------------------------------------------------------------
__global__ __launch_bounds__(256, 4)
void compute_c_kernel(const float* __restrict__ P, float* __restrict__ C)
{
    const size_t idx = (size_t)blockIdx.x * 256 + threadIdx.x;  // float4 index
    const int row  = (int)(idx >> 10);
    const int col4 = (int)(idx & 1023);

    const float a  = g_AF[row];
    const float4 p = reinterpret_cast<const float4*>(P)[idx];
    const float4 b = *reinterpret_cast<const float4*>(&g_BF[col4 * 4]);

    float4 o;
    o.x = p.x * p.x * a * b.x;
    o.y = p.y * p.y * a * b.y;
    o.z = p.z * p.z * a * b.z;
    o.w = p.w * p.w * a * b.w;
    reinterpret_cast<float4*>(C)[idx] = o;
}

// ---------------------------------------------------------------------------
// 21 x {iter, bf_fin} + C = 43 graph nodes. No sync/alloc/memcpy/fences.
// cudaFuncSetAttribute is idempotent and capture-legal (not a stream op).
// ---------------------------------------------------------------------------
extern "C" void kernel_launch(void* const* d_in, const int* in_sizes, int n_in,
                              void* d_out, int out_size)
{
    const float* AT = (const float*)d_in[0];   // [4096]
    const float* BT = (const float*)d_in[1];   // [4096]
    const float* P  = (const float*)d_in[2];   // [4096, 4096]
    float* C = (float*)d_out;                  // [4096, 4096]

    cudaFuncSetAttribute(iter_kernel,
                         cudaFuncAttributeMaxDynamicSharedMemorySize, SMEM_IT);

    for (int it = 0; it < NITER; it++) {
        iter_kernel<<<NBLK_IT, NTHR, SMEM_IT>>>(P, AT, BT, it == 0 ? 1 : 0);
        bf_fin_kernel<<<N / 256, 256>>>(BT);
    }
    compute_c_kernel<<<((size_t)N * (N / 4)) / 256, 256>>>(P, C);
}

// round 13
// speedup vs baseline: 2.0530x; 2.0530x over previous
#include <cuda_runtime.h>
#include <cuda_fp16.h>

// CompetitiveLayer: 21 x { AF = AT/(1+K@BF); BF = BT/(1+AF@K) }, K = param^2,
// then C = param^2 * AF[:,None] * BF[None,:].
//
// Attribution so far:
//  - iter_kernel (R11): reads fp16 K ONCE per iteration, reuses the 8x4096
//    tile from smem for the column partials -> ~2.9us/iteration INCLUDING the
//    node gap. Keep verbatim.
//  - R11 finalize (grid=8, serial 512 loads/thread): 26.3us, latency-bound.
//  - R12 u64-atomic accumulation: 4096 hot addresses x 512 contenders ->
//    LTS atomic serialization, ~33us/iter. Banned.
// Fix: parallel deterministic 2-stage finalize — 64 blocks x 256 threads,
// 8 chunk-groups per column pair reduced in fixed order. ~4MB traffic, ~1.5us.

#define N        4096
#define NITER    21
#define R        8                 // rows per iteration block
#define NBLK_IT  (N / R)           // 512 blocks
#define NTHR     256

// smem layout: sBF (fp32, 16KB) | tile (fp16, 64KB) | sAFloc (8 floats)
#define SMEM_IT  (N * 4 + R * N * 2 + 64)

// Scratch — __device__ globals (no cudaMalloc allowed)
__device__ __half g_Kh[(size_t)N * N];          // fp16 param^2 (32 MB)
__device__ float  g_AF[N];
__device__ float  g_BF[N];
__device__ __half g_tmph[(size_t)NBLK_IT * N];  // column partials (4 MB)

// ---------------------------------------------------------------------------
// Per-iteration kernel. Block b owns rows [8b, 8b+8).
//   pass 1 (warp per row): AF[i] = AT[i]/(1 + Kh[i,:].BF); tile row -> smem.
//           first==1: read P fp32, square, convert; also persist to g_Kh.
//   pass 2 (thread per 16 cols): tmph[b][j] = sum_{r<8} AF_loc[r]*tile[r][j].
// No cross-block communication, no atomics, no fences.
// ---------------------------------------------------------------------------
__global__ __launch_bounds__(NTHR)
void iter_kernel(const float* __restrict__ P,
                 const float* __restrict__ AT,
                 const float* __restrict__ BT,
                 int first)
{
    extern __shared__ __align__(16) char smem_raw[];
    float*  sBF    = reinterpret_cast<float*>(smem_raw);                 // [N]
    __half* tile   = reinterpret_cast<__half*>(smem_raw + N * 4);        // [R*N]
    float*  sAFloc = reinterpret_cast<float*>(smem_raw + N * 4 + R * N * 2);

    const int tid  = threadIdx.x;
    const int bid  = blockIdx.x;
    const int warp = tid >> 5;
    const int lane = tid & 31;

    // ---- stage BF (fp32) into smem ----
    {
        const float4* src = first ? reinterpret_cast<const float4*>(BT)
                                  : reinterpret_cast<const float4*>(g_BF);
        float4* dst = reinterpret_cast<float4*>(sBF);
        #pragma unroll
        for (int i = tid; i < N / 4; i += NTHR) dst[i] = src[i];
    }
    __syncthreads();

    // ---- pass 1: one row per warp ----
    const int row = bid * R + warp;
    uint4* krow_s = reinterpret_cast<uint4*>(tile + warp * N);
    float acc = 0.f;

    if (first) {
        const float4* prow = reinterpret_cast<const float4*>(P + ((size_t)row << 12));
        uint4* krow_g = reinterpret_cast<uint4*>(g_Kh + ((size_t)row << 12));
        #pragma unroll
        for (int j = lane; j < N / 8; j += 32) {          // 16 trips
            float4 a = prow[2 * j];
            float4 b = prow[2 * j + 1];
            float s0 = a.x * a.x, s1 = a.y * a.y, s2 = a.z * a.z, s3 = a.w * a.w;
            float s4 = b.x * b.x, s5 = b.y * b.y, s6 = b.z * b.z, s7 = b.w * b.w;
            const float* bf = &sBF[j * 8];
            acc = fmaf(s0, bf[0], acc); acc = fmaf(s1, bf[1], acc);
            acc = fmaf(s2, bf[2], acc); acc = fmaf(s3, bf[3], acc);
            acc = fmaf(s4, bf[4], acc); acc = fmaf(s5, bf[5], acc);
            acc = fmaf(s6, bf[6], acc); acc = fmaf(s7, bf[7], acc);
            __half2 h0 = __floats2half2_rn(s0, s1);
            __half2 h1 = __floats2half2_rn(s2, s3);
            __half2 h2 = __floats2half2_rn(s4, s5);
            __half2 h3 = __floats2half2_rn(s6, s7);
            uint4 v;
            v.x = *reinterpret_cast<unsigned*>(&h0);
            v.y = *reinterpret_cast<unsigned*>(&h1);
            v.z = *reinterpret_cast<unsigned*>(&h2);
            v.w = *reinterpret_cast<unsigned*>(&h3);
            krow_s[j] = v;
            __stcg(&krow_g[j], v);    // persist fp16 K for later iterations
        }
    } else {
        const uint4* krow_g = reinterpret_cast<const uint4*>(g_Kh + ((size_t)row << 12));
        #pragma unroll
        for (int j = lane; j < N / 8; j += 32) {          // 16 trips, 16B each
            uint4 v = krow_g[j];
            krow_s[j] = v;
            const float* bf = &sBF[j * 8];
            float2 f0 = __half22float2(*reinterpret_cast<__half2*>(&v.x));
            float2 f1 = __half22float2(*reinterpret_cast<__half2*>(&v.y));
            float2 f2 = __half22float2(*reinterpret_cast<__half2*>(&v.z));
            float2 f3 = __half22float2(*reinterpret_cast<__half2*>(&v.w));
            acc = fmaf(f0.x, bf[0], acc); acc = fmaf(f0.y, bf[1], acc);
            acc = fmaf(f1.x, bf[2], acc); acc = fmaf(f1.y, bf[3], acc);
            acc = fmaf(f2.x, bf[4], acc); acc = fmaf(f2.y, bf[5], acc);
            acc = fmaf(f3.x, bf[6], acc); acc = fmaf(f3.y, bf[7], acc);
        }
    }
    #pragma unroll
    for (int o = 16; o > 0; o >>= 1) acc += __shfl_xor_sync(0xFFFFFFFFu, acc, o);
    if (lane == 0) {
        float af = AT[row] / (1.0f + acc);
        sAFloc[warp] = af;
        __stcg(&g_AF[row], af);       // for later iterations / final C
    }
    __syncthreads();

    // ---- pass 2: column partials from smem tile; thread owns 16 cols ----
    {
        const int j0 = tid * 16;                           // half index
        float accc[16];
        #pragma unroll
        for (int k = 0; k < 16; k++) accc[k] = 0.f;

        #pragma unroll
        for (int r = 0; r < R; r++) {                      // fixed order
            const float a = sAFloc[r];
            uint4 v0 = *reinterpret_cast<const uint4*>(tile + r * N + j0);
            uint4 v1 = *reinterpret_cast<const uint4*>(tile + r * N + j0 + 8);
            float2 f;
            f = __half22float2(*reinterpret_cast<__half2*>(&v0.x));
            accc[0]  = fmaf(a, f.x, accc[0]);  accc[1]  = fmaf(a, f.y, accc[1]);
            f = __half22float2(*reinterpret_cast<__half2*>(&v0.y));
            accc[2]  = fmaf(a, f.x, accc[2]);  accc[3]  = fmaf(a, f.y, accc[3]);
            f = __half22float2(*reinterpret_cast<__half2*>(&v0.z));
            accc[4]  = fmaf(a, f.x, accc[4]);  accc[5]  = fmaf(a, f.y, accc[5]);
            f = __half22float2(*reinterpret_cast<__half2*>(&v0.w));
            accc[6]  = fmaf(a, f.x, accc[6]);  accc[7]  = fmaf(a, f.y, accc[7]);
            f = __half22float2(*reinterpret_cast<__half2*>(&v1.x));
            accc[8]  = fmaf(a, f.x, accc[8]);  accc[9]  = fmaf(a, f.y, accc[9]);
            f = __half22float2(*reinterpret_cast<__half2*>(&v1.y));
            accc[10] = fmaf(a, f.x, accc[10]); accc[11] = fmaf(a, f.y, accc[11]);
            f = __half22float2(*reinterpret_cast<__half2*>(&v1.z));
            accc[12] = fmaf(a, f.x, accc[12]); accc[13] = fmaf(a, f.y, accc[13]);
            f = __half22float2(*reinterpret_cast<__half2*>(&v1.w));
            accc[14] = fmaf(a, f.x, accc[14]); accc[15] = fmaf(a, f.y, accc[15]);
        }

        __half2 h[8];
        #pragma unroll
        for (int k = 0; k < 8; k++)
            h[k] = __floats2half2_rn(accc[2 * k], accc[2 * k + 1]);
        uint4 o0, o1;
        o0.x = *reinterpret_cast<unsigned*>(&h[0]);
        o0.y = *reinterpret_cast<unsigned*>(&h[1]);
        o0.z = *reinterpret_cast<unsigned*>(&h[2]);
        o0.w = *reinterpret_cast<unsigned*>(&h[3]);
        o1.x = *reinterpret_cast<unsigned*>(&h[4]);
        o1.y = *reinterpret_cast<unsigned*>(&h[5]);
        o1.z = *reinterpret_cast<unsigned*>(&h[6]);
        o1.w = *reinterpret_cast<unsigned*>(&h[7]);
        uint4* dst = reinterpret_cast<uint4*>(g_tmph + (size_t)bid * N + j0);
        __stcg(&dst[0], o0);
        __stcg(&dst[1], o1);
    }
}

// ---------------------------------------------------------------------------
// Finalize: BF[j] = BT[j] / (1 + sum_{c<512} tmph[c][j]).
// grid = 64 blocks x 256 threads. Block owns 64 columns (32 half2 pairs).
// Thread (g = tid>>5, p = tid&31) sums chunks c in {g, g+8, ..., g+504}
// (64 half2 loads, warp loads 128B contiguous, unroll 8 -> MLP hides L2 lat).
// Stage 2: 32 threads reduce the 8 group-partials per pair IN FIXED g ORDER
// -> bitwise deterministic. No atomics, no fences.
// ---------------------------------------------------------------------------
__global__ __launch_bounds__(256, 4)
void finalize_bf_kernel(const float* __restrict__ BT)
{
    __shared__ float2 sPart[8][32];

    const int tid = threadIdx.x;
    const int g   = tid >> 5;          // chunk group 0..7
    const int p   = tid & 31;          // column pair within block
    const int pairBase = blockIdx.x * 32;            // half2 index base

    const __half2* t2 = reinterpret_cast<const __half2*>(g_tmph);

    float2 acc = make_float2(0.f, 0.f);
    #pragma unroll 8
    for (int c = g; c < NBLK_IT; c += 8) {           // 64 trips
        __half2 hv = __ldcg(&t2[(size_t)c * (N / 2) + pairBase + p]);
        float2 f = __half22float2(hv);
        acc.x += f.x;
        acc.y += f.y;
    }
    sPart[g][p] = acc;
    __syncthreads();

    if (tid < 32) {
        float2 s = make_float2(0.f, 0.f);
        #pragma unroll
        for (int gg = 0; gg < 8; gg++) {             // fixed order
            float2 v = sPart[gg][tid];
            s.x += v.x;
            s.y += v.y;
        }
        const int j = (pairBase + tid) * 2;
        const float2 bt = *reinterpret_cast<const float2*>(&BT[j]);
        float2 out;
        out.x = bt.x / (1.0f + s.x);
        out.y = bt.y / (1.0f + s.y);
        *reinterpret_cast<float2*>(&g_BF[j]) = out;
    }
}

// ---------------------------------------------------------------------------
// Output: C[i][j] = param[i][j]^2 * AF[i] * BF[j]  — exact fp32 K.
// ---------------------------------------------------------------------------
__global__ __launch_bounds__(256, 4)
void compute_c_kernel(const float* __restrict__ P, float* __restrict__ C)
{
    const size_t idx = (size_t)blockIdx.x * 256 + threadIdx.x;  // float4 index
    const int row  = (int)(idx >> 10);
    const int col4 = (int)(idx & 1023);

    const float a  = g_AF[row];
    const float4 p = reinterpret_cast<const float4*>(P)[idx];
    const float4 b = *reinterpret_cast<const float4*>(&g_BF[col4 * 4]);

    float4 o;
    o.x = p.x * p.x * a * b.x;
    o.y = p.y * p.y * a * b.y;
    o.z = p.z * p.z * a * b.z;
    o.w = p.w * p.w * a * b.w;
    reinterpret_cast<float4*>(C)[idx] = o;
}

// ---------------------------------------------------------------------------
// 21 x {iter, finalize} + C = 43 graph nodes. No sync/alloc/memcpy/fences.
// cudaFuncSetAttribute is idempotent and capture-legal (not a stream op).
// ---------------------------------------------------------------------------
extern "C" void kernel_launch(void* const* d_in, const int* in_sizes, int n_in,
                              void* d_out, int out_size)
{
    const float* AT = (const float*)d_in[0];   // [4096]
    const float* BT = (const float*)d_in[1];   // [4096]
    const float* P  = (const float*)d_in[2];   // [4096, 4096]
    float* C = (float*)d_out;                  // [4096, 4096]

    cudaFuncSetAttribute(iter_kernel,
                         cudaFuncAttributeMaxDynamicSharedMemorySize, SMEM_IT);

    for (int it = 0; it < NITER; it++) {
        iter_kernel<<<NBLK_IT, NTHR, SMEM_IT>>>(P, AT, BT, it == 0 ? 1 : 0);
        finalize_bf_kernel<<<N / 64, 256>>>(BT);
    }
    compute_c_kernel<<<((size_t)N * (N / 4)) / 256, 256>>>(P, C);
}

// round 14
// speedup vs baseline: 2.1937x; 1.0685x over previous
#include <cuda_runtime.h>
#include <cuda_fp16.h>

// CompetitiveLayer: 21 x { AF = AT/(1+K@BF); BF = BT/(1+AF@K) }, K = param^2,
// then C = param^2 * AF[:,None] * BF[None,:].
//
// Lessons R9-R13: every fancy column-reduction (grid barrier, threadfence
// last-CTA, u64 atomics, fused smem-tile kernel) lost to the plain R8
// warp-per-row streaming matvec + kernel boundaries. So: make BOTH directions
// that shape. One-time prep builds fp16 K^2 AND its transpose (32 MB each,
// both L2-resident). Each iteration is just two identical row-matvec kernels:
//   AF = AT / (1 + Kh  @ BF)        (rows of Kh)
//   BF = BT / (1 + KhT @ AF)        (rows of KhT = columns of Kh)
// No partials, no finalize kernel, no atomics, no fences. 44 graph nodes.
// Final C uses exact fp32 param^2 (fp16 only perturbs AF/BF, ~1e-5 rel).

#define N     4096
#define NITER 21

// Scratch — __device__ globals (no cudaMalloc allowed)
__device__ __half g_Kh [(size_t)N * N];   // fp16 param^2            (32 MB)
__device__ __half g_KhT[(size_t)N * N];   // fp16 param^2 transposed (32 MB)
__device__ float  g_AF[N];
__device__ float  g_BF[N];

// ---------------------------------------------------------------------------
// Prep: square P, write Kh (direct) and KhT (via 64x64 smem tile transpose).
// grid = (64, 64) tiles, 256 threads. Runs once (~128 MB traffic).
// ---------------------------------------------------------------------------
__global__ __launch_bounds__(256, 4)
void prep_kernel(const float* __restrict__ P)
{
    __shared__ __align__(16) __half tile[64][72];   // +8 pad vs bank conflicts

    const int bx  = blockIdx.x;        // column tile
    const int by  = blockIdx.y;        // row tile
    const int tid = threadIdx.x;

    const float4* P4    = reinterpret_cast<const float4*>(P);
    uint2*        Kh2   = reinterpret_cast<uint2*>(g_Kh);
    uint2*        KhT2  = reinterpret_cast<uint2*>(g_KhT);

    #pragma unroll
    for (int pass = 0; pass < 4; pass++) {
        const int r  = (pass << 4) + (tid >> 4);    // 0..63 row in tile
        const int c4 = tid & 15;                    // float4 column in tile
        const size_t grow = (size_t)(by * 64 + r);
        float4 v = P4[grow * 1024 + bx * 16 + c4];

        __half2 h0 = __floats2half2_rn(v.x * v.x, v.y * v.y);
        __half2 h1 = __floats2half2_rn(v.z * v.z, v.w * v.w);
        uint2 u;
        u.x = *reinterpret_cast<unsigned*>(&h0);
        u.y = *reinterpret_cast<unsigned*>(&h1);

        Kh2[grow * 1024 + bx * 16 + c4] = u;                       // coalesced
        *reinterpret_cast<uint2*>(&tile[r][c4 * 4]) = u;           // stage
    }
    __syncthreads();

    #pragma unroll
    for (int pass = 0; pass < 4; pass++) {
        const int r  = (pass << 4) + (tid >> 4);    // KhT row within tile
        const int c4 = tid & 15;                    // group of 4 source rows
        __half a0 = tile[c4 * 4 + 0][r];
        __half a1 = tile[c4 * 4 + 1][r];
        __half a2 = tile[c4 * 4 + 2][r];
        __half a3 = tile[c4 * 4 + 3][r];
        __half2 h0 = __halves2half2(a0, a1);
        __half2 h1 = __halves2half2(a2, a3);
        uint2 u;
        u.x = *reinterpret_cast<unsigned*>(&h0);
        u.y = *reinterpret_cast<unsigned*>(&h1);
        KhT2[(size_t)(bx * 64 + r) * 1024 + by * 16 + c4] = u;     // coalesced
    }
}

// ---------------------------------------------------------------------------
// Row matvec (both directions): dst[i] = numer[i] / (1 + M[i,:] . vec)
//   useT=0: M=Kh,  vec = (use_init ? init_vec : g_BF), dst = g_AF
//   useT=1: M=KhT, vec = g_AF,                          dst = g_BF
// 1 warp per row, 8 rows / 256-thread block, vec staged in smem (fp32).
// grid = 512 blocks. Fixed reduction order -> deterministic.
// ---------------------------------------------------------------------------
__global__ __launch_bounds__(256, 2)
void row_mv_kernel(int useT,
                   const float* __restrict__ numer,
                   const float* __restrict__ init_vec,
                   int use_init)
{
    __shared__ float sV[N];   // 16 KB

    const int tid = threadIdx.x;

    const __half* M   = useT ? g_KhT : g_Kh;
    const float*  vec = use_init ? init_vec : (useT ? g_AF : g_BF);
    float*        dst = useT ? g_BF : g_AF;

    {
        const float4* src = reinterpret_cast<const float4*>(vec);
        float4* dst4 = reinterpret_cast<float4*>(sV);
        #pragma unroll
        for (int i = tid; i < N / 4; i += 256) dst4[i] = src[i];
    }
    __syncthreads();

    const int warp = tid >> 5;
    const int lane = tid & 31;
    const int row  = blockIdx.x * 8 + warp;

    const uint4* mrow = reinterpret_cast<const uint4*>(M + ((size_t)row << 12));

    float acc = 0.f;
    #pragma unroll 8
    for (int j = lane; j < N / 8; j += 32) {      // 16 trips, 16B each
        uint4 v = mrow[j];
        const float* b = &sV[j * 8];
        float2 f0 = __half22float2(*reinterpret_cast<__half2*>(&v.x));
        float2 f1 = __half22float2(*reinterpret_cast<__half2*>(&v.y));
        float2 f2 = __half22float2(*reinterpret_cast<__half2*>(&v.z));
        float2 f3 = __half22float2(*reinterpret_cast<__half2*>(&v.w));
        acc = fmaf(f0.x, b[0], acc);
        acc = fmaf(f0.y, b[1], acc);
        acc = fmaf(f1.x, b[2], acc);
        acc = fmaf(f1.y, b[3], acc);
        acc = fmaf(f2.x, b[4], acc);
        acc = fmaf(f2.y, b[5], acc);
        acc = fmaf(f3.x, b[6], acc);
        acc = fmaf(f3.y, b[7], acc);
    }
    #pragma unroll
    for (int o = 16; o > 0; o >>= 1) acc += __shfl_xor_sync(0xFFFFFFFFu, acc, o);

    if (lane == 0) dst[row] = numer[row] / (1.0f + acc);
}

// ---------------------------------------------------------------------------
// Output: C[i][j] = param[i][j]^2 * AF[i] * BF[j]  — exact fp32 K.
// ---------------------------------------------------------------------------
__global__ __launch_bounds__(256, 4)
void compute_c_kernel(const float* __restrict__ P, float* __restrict__ C)
{
    const size_t idx = (size_t)blockIdx.x * 256 + threadIdx.x;  // float4 index
    const int row  = (int)(idx >> 10);
    const int col4 = (int)(idx & 1023);

    const float a  = g_AF[row];
    const float4 p = reinterpret_cast<const float4*>(P)[idx];
    const float4 b = *reinterpret_cast<const float4*>(&g_BF[col4 * 4]);

    float4 o;
    o.x = p.x * p.x * a * b.x;
    o.y = p.y * p.y * a * b.y;
    o.z = p.z * p.z * a * b.z;
    o.w = p.w * p.w * a * b.w;
    reinterpret_cast<float4*>(C)[idx] = o;
}

// ---------------------------------------------------------------------------
// prep + 21 x {rowA, rowB} + C = 44 graph nodes.
// Default stream only; no sync, no alloc, no memcpy, no fences, no atomics.
// ---------------------------------------------------------------------------
extern "C" void kernel_launch(void* const* d_in, const int* in_sizes, int n_in,
                              void* d_out, int out_size)
{
    const float* AT = (const float*)d_in[0];   // [4096]
    const float* BT = (const float*)d_in[1];   // [4096]
    const float* P  = (const float*)d_in[2];   // [4096, 4096]
    float* C = (float*)d_out;                  // [4096, 4096]

    prep_kernel<<<dim3(64, 64), 256>>>(P);

    for (int it = 0; it < NITER; it++) {
        // AF = AT / (1 + Kh @ BF)   (BF := BT on the first iteration)
        row_mv_kernel<<<N / 8, 256>>>(0, AT, BT, it == 0 ? 1 : 0);
        // BF = BT / (1 + KhT @ AF)
        row_mv_kernel<<<N / 8, 256>>>(1, BT, BT, 0);
    }
    compute_c_kernel<<<((size_t)N * (N / 4)) / 256, 256>>>(P, C);
}

// round 15
// speedup vs baseline: 2.6371x; 1.2021x over previous
#include <cuda_runtime.h>
#include <cuda_fp16.h>

// CompetitiveLayer: 21 x { AF = AT/(1+K@BF); BF = BT/(1+AF@K) }, K = param^2,
// then C = param^2 * AF[:,None] * BF[None,:].
//
// R14 conclusion: the R8 kernel set (fp16 K, warp-per-row matvec, 2-stage
// deterministic column reduce) is the cheapest per byte; the remaining loss
// is ~1.5-2us of dead time at each of the 63 node boundaries. This round
// keeps R8's kernels VERBATIM in structure and hides the boundaries with
// Programmatic Dependent Launch (PSS attribute + cudaGridDependencySynchronize
// at the top of every kernel). If the attribute is ignored, semantics are
// plain stream order -> identical results, R8 timing. No atomics, no fences.

#define N        4096
#define NITER    21
#define ROW_CHUNKS 16
#define CHUNK_ROWS (N / ROW_CHUNKS)   // 256
#define COL_TILE   256

// Scratch — __device__ globals (no cudaMalloc allowed)
__device__ __half g_Kh[(size_t)N * N];   // fp16 param^2 (32 MB, L2-resident)
__device__ float  g_AF[N];
__device__ float  g_BF[N];
__device__ float  g_tmp[ROW_CHUNKS * N];

// ---------------------------------------------------------------------------
// Prep: g_Kh[i][j] = (half)(P[i][j]^2).  One thread = 8 elements.
// ---------------------------------------------------------------------------
__global__ __launch_bounds__(256, 4)
void prep_kh_kernel(const float* __restrict__ P)
{
    const size_t idx = (size_t)blockIdx.x * 256 + threadIdx.x;  // unit: 8 floats
    const float4* p4 = reinterpret_cast<const float4*>(P);
    float4 a = p4[2 * idx];
    float4 b = p4[2 * idx + 1];

    __half2 h0 = __floats2half2_rn(a.x * a.x, a.y * a.y);
    __half2 h1 = __floats2half2_rn(a.z * a.z, a.w * a.w);
    __half2 h2 = __floats2half2_rn(b.x * b.x, b.y * b.y);
    __half2 h3 = __floats2half2_rn(b.z * b.z, b.w * b.w);

    uint4 out;
    out.x = *reinterpret_cast<unsigned*>(&h0);
    out.y = *reinterpret_cast<unsigned*>(&h1);
    out.z = *reinterpret_cast<unsigned*>(&h2);
    out.w = *reinterpret_cast<unsigned*>(&h3);
    reinterpret_cast<uint4*>(g_Kh)[idx] = out;
}

// ---------------------------------------------------------------------------
// Row matvec: AF[i] = AT[i] / (1 + Kh[i,:] . BF)
// 1 warp per row, 8 rows per 256-thread block, BF staged in shared.
// grid = 512. PDL: gridsync before any dependent global read.
// ---------------------------------------------------------------------------
__global__ __launch_bounds__(256, 2)
void row_mv_kernel(const float* __restrict__ AT,
                   const float* __restrict__ BT,
                   int use_bt)
{
    __shared__ float sBF[N];   // 16 KB

    cudaGridDependencySynchronize();   // wait for predecessor's writes

    const int tid = threadIdx.x;
    const float* BFin = use_bt ? BT : g_BF;
    const float4* bf4 = reinterpret_cast<const float4*>(BFin);
    float4* sbf4 = reinterpret_cast<float4*>(sBF);
    #pragma unroll
    for (int i = tid; i < N / 4; i += 256) sbf4[i] = bf4[i];
    __syncthreads();

    const int warp = tid >> 5;
    const int lane = tid & 31;
    const int row  = blockIdx.x * 8 + warp;

    const uint4* prow = reinterpret_cast<const uint4*>(g_Kh + ((size_t)row << 12));

    float acc = 0.f;
    #pragma unroll 8
    for (int j = lane; j < N / 8; j += 32) {      // 16 trips, 16B each
        uint4 v = prow[j];
        const float* b = &sBF[j * 8];
        float2 f0 = __half22float2(*reinterpret_cast<__half2*>(&v.x));
        float2 f1 = __half22float2(*reinterpret_cast<__half2*>(&v.y));
        float2 f2 = __half22float2(*reinterpret_cast<__half2*>(&v.z));
        float2 f3 = __half22float2(*reinterpret_cast<__half2*>(&v.w));
        acc = fmaf(f0.x, b[0], acc);
        acc = fmaf(f0.y, b[1], acc);
        acc = fmaf(f1.x, b[2], acc);
        acc = fmaf(f1.y, b[3], acc);
        acc = fmaf(f2.x, b[4], acc);
        acc = fmaf(f2.y, b[5], acc);
        acc = fmaf(f3.x, b[6], acc);
        acc = fmaf(f3.y, b[7], acc);
    }
    #pragma unroll
    for (int o = 16; o > 0; o >>= 1) acc += __shfl_xor_sync(0xFFFFFFFFu, acc, o);

    if (lane == 0) g_AF[row] = AT[row] / (1.0f + acc);
}

// ---------------------------------------------------------------------------
// Col matvec partial: tmp[cy][j] = sum_{i in chunk cy} AF[i] * Kh[i][j]
// grid = (16 col-tiles, 16 row-chunks). fp32 partials via L2 (__stcg).
// ---------------------------------------------------------------------------
__global__ __launch_bounds__(256, 4)
void col_mv_partial_kernel()
{
    __shared__ float sAF[CHUNK_ROWS];     // 1 KB
    __shared__ float sAcc[8 * COL_TILE];  // 8 KB

    cudaGridDependencySynchronize();   // AF must be complete

    const int tid     = threadIdx.x;
    const int warp    = tid >> 5;
    const int lane    = tid & 31;
    const int colBase = blockIdx.x * COL_TILE;
    const int rowBase = blockIdx.y * CHUNK_ROWS;

    if (tid < CHUNK_ROWS) sAF[tid] = g_AF[rowBase + tid];
    __syncthreads();

    float acc[8];
    #pragma unroll
    for (int k = 0; k < 8; k++) acc[k] = 0.f;

    #pragma unroll 4
    for (int s = 0; s < CHUNK_ROWS / 8; s++) {    // 32 trips
        const int r = warp + 8 * s;
        const float a = sAF[r];
        uint4 v = *reinterpret_cast<const uint4*>(
            g_Kh + (((size_t)(rowBase + r)) << 12) + colBase + 8 * lane);
        float2 f0 = __half22float2(*reinterpret_cast<__half2*>(&v.x));
        float2 f1 = __half22float2(*reinterpret_cast<__half2*>(&v.y));
        float2 f2 = __half22float2(*reinterpret_cast<__half2*>(&v.z));
        float2 f3 = __half22float2(*reinterpret_cast<__half2*>(&v.w));
        acc[0] = fmaf(a, f0.x, acc[0]);
        acc[1] = fmaf(a, f0.y, acc[1]);
        acc[2] = fmaf(a, f1.x, acc[2]);
        acc[3] = fmaf(a, f1.y, acc[3]);
        acc[4] = fmaf(a, f2.x, acc[4]);
        acc[5] = fmaf(a, f2.y, acc[5]);
        acc[6] = fmaf(a, f3.x, acc[6]);
        acc[7] = fmaf(a, f3.y, acc[7]);
    }

    #pragma unroll
    for (int k = 0; k < 8; k++) sAcc[warp * 256 + lane * 8 + k] = acc[k];
    __syncthreads();

    // Fixed-order cross-warp reduce; thread t owns column colBase + t.
    float s = 0.f;
    #pragma unroll
    for (int w = 0; w < 8; w++) s += sAcc[w * 256 + tid];
    __stcg(&g_tmp[blockIdx.y * N + colBase + tid], s);
}

// ---------------------------------------------------------------------------
// Finalize: BF[j] = BT[j] / (1 + sum_cy tmp[cy][j]).  grid = 16 x 256.
// ---------------------------------------------------------------------------
__global__ __launch_bounds__(256, 4)
void finalize_bf_kernel(const float* __restrict__ BT)
{
    cudaGridDependencySynchronize();   // all partials complete

    const int j = blockIdx.x * 256 + threadIdx.x;
    float s = 0.f;
    #pragma unroll
    for (int c = 0; c < ROW_CHUNKS; c++) s += __ldcg(&g_tmp[c * N + j]);
    g_BF[j] = BT[j] / (1.0f + s);
}

// ---------------------------------------------------------------------------
// Output: C[i][j] = param[i][j]^2 * AF[i] * BF[j]  — exact fp32 K.
// ---------------------------------------------------------------------------
__global__ __launch_bounds__(256, 4)
void compute_c_kernel(const float* __restrict__ P, float* __restrict__ C)
{
    cudaGridDependencySynchronize();   // final BF complete

    const size_t idx = (size_t)blockIdx.x * 256 + threadIdx.x;  // float4 index
    const int row  = (int)(idx >> 10);
    const int col4 = (int)(idx & 1023);

    const float a  = g_AF[row];
    const float4 p = reinterpret_cast<const float4*>(P)[idx];
    const float4 b = *reinterpret_cast<const float4*>(&g_BF[col4 * 4]);

    float4 o;
    o.x = p.x * p.x * a * b.x;
    o.y = p.y * p.y * a * b.y;
    o.z = p.z * p.z * a * b.z;
    o.w = p.w * p.w * a * b.w;
    reinterpret_cast<float4*>(C)[idx] = o;
}

// ---------------------------------------------------------------------------
// PDL launch helper: every node allows programmatic stream serialization so
// the successor's launch/ramp overlaps the predecessor's tail. Stream-order
// memory semantics are preserved by cudaGridDependencySynchronize() in each
// kernel. Capture-legal (kernel launches only).
// ---------------------------------------------------------------------------
template <typename K, typename... Args>
static inline void launch_pdl(K kernel, dim3 grid, dim3 block, Args... args)
{
    cudaLaunchConfig_t cfg = {};
    cfg.gridDim  = grid;
    cfg.blockDim = block;
    cudaLaunchAttribute attr[1];
    attr[0].id = cudaLaunchAttributeProgrammaticStreamSerialization;
    attr[0].val.programmaticStreamSerializationAllowed = 1;
    cfg.attrs    = attr;
    cfg.numAttrs = 1;
    cudaLaunchKernelEx(&cfg, kernel, args...);
}

// ---------------------------------------------------------------------------
// prep + 21 x {rowMV, colMV, finalize} + C = 65 graph nodes, boundaries
// hidden by PDL. No sync, no alloc, no memcpy, no fences, no atomics.
// ---------------------------------------------------------------------------
extern "C" void kernel_launch(void* const* d_in, const int* in_sizes, int n_in,
                              void* d_out, int out_size)
{
    const float* AT = (const float*)d_in[0];   // [4096]
    const float* BT = (const float*)d_in[1];   // [4096]
    const float* P  = (const float*)d_in[2];   // [4096, 4096]
    float* C = (float*)d_out;                  // [4096, 4096]

    launch_pdl(prep_kh_kernel, dim3((unsigned)(((size_t)N * N / 8) / 256)),
               dim3(256), P);

    const dim3 colGrid(16, ROW_CHUNKS);

    for (int it = 0; it < NITER; it++) {
        launch_pdl(row_mv_kernel, dim3(N / 8), dim3(256),
                   AT, BT, it == 0 ? 1 : 0);
        launch_pdl(col_mv_partial_kernel, colGrid, dim3(256));
        launch_pdl(finalize_bf_kernel, dim3(N / 256), dim3(256), BT);
    }
    launch_pdl(compute_c_kernel,
               dim3((unsigned)(((size_t)N * (N / 4)) / 256)), dim3(256), P, C);
}

// round 17
// speedup vs baseline: 2.6681x; 1.0118x over previous
#include <cuda_runtime.h>
#include <cuda_fp16.h>

// CompetitiveLayer: 21 x { AF = AT/(1+K@BF); BF = BT/(1+AF@K) }, K = param^2,
// then C = param^2 * AF[:,None] * BF[None,:].
//
// R16 post-mortem: trigger-at-top broke PDL memory semantics (writes after
// the trigger are NOT visible to the successor's gridsync) -> stale BF/AF,
// rel_err 3.5e-2. Fix: NO explicit triggers (implicit trigger at block
// completion = exact stream-order visibility, proven in R15 @303us), but KEEP
// prefetch-before-gridsync of immutable data (Kh / P) — that part is legal:
// with PSS the successor starts during the predecessor's tail and streams
// read-only bytes early; only dependent vector reads sit behind gridsync.

#define N        4096
#define NITER    21
#define ROW_CHUNKS 16
#define CHUNK_ROWS (N / ROW_CHUNKS)   // 256
#define COL_TILE   256

// Scratch — __device__ globals (no cudaMalloc allowed)
__device__ __half g_Kh[(size_t)N * N];   // fp16 param^2 (32 MB, L2-resident)
__device__ float  g_AF[N];
__device__ float  g_BF[N];
__device__ float  g_tmp[ROW_CHUNKS * N];

// ---------------------------------------------------------------------------
// Prep: g_Kh[i][j] = (half)(P[i][j]^2).  One thread = 8 elements.
// ---------------------------------------------------------------------------
__global__ __launch_bounds__(256, 4)
void prep_kh_kernel(const float* __restrict__ P)
{
    const size_t idx = (size_t)blockIdx.x * 256 + threadIdx.x;  // unit: 8 floats
    const float4* p4 = reinterpret_cast<const float4*>(P);
    float4 a = p4[2 * idx];
    float4 b = p4[2 * idx + 1];

    __half2 h0 = __floats2half2_rn(a.x * a.x, a.y * a.y);
    __half2 h1 = __floats2half2_rn(a.z * a.z, a.w * a.w);
    __half2 h2 = __floats2half2_rn(b.x * b.x, b.y * b.y);
    __half2 h3 = __floats2half2_rn(b.z * b.z, b.w * b.w);

    uint4 out;
    out.x = *reinterpret_cast<unsigned*>(&h0);
    out.y = *reinterpret_cast<unsigned*>(&h1);
    out.z = *reinterpret_cast<unsigned*>(&h2);
    out.w = *reinterpret_cast<unsigned*>(&h3);
    reinterpret_cast<uint4*>(g_Kh)[idx] = out;
}

// ---------------------------------------------------------------------------
// Row matvec: AF[i] = AT[i] / (1 + Kh[i,:] . BF)
// 1 warp per row, 8 rows / 256-thread block, BF staged in shared. grid = 512.
// PDL: prefetch first 8 Kh uint4s (immutable) BEFORE gridsync, except on
// iteration 0 where the predecessor (prep) is still writing Kh.
// ---------------------------------------------------------------------------
__global__ __launch_bounds__(256, 2)
void row_mv_kernel(const float* __restrict__ AT,
                   const float* __restrict__ BT,
                   int use_bt)
{
    __shared__ float sBF[N];   // 16 KB

    const int tid  = threadIdx.x;
    const int warp = tid >> 5;
    const int lane = tid & 31;
    const int row  = blockIdx.x * 8 + warp;

    const uint4* prow = reinterpret_cast<const uint4*>(g_Kh + ((size_t)row << 12));

    // Early streaming of immutable Kh while the predecessor drains.
    uint4 pf[8];
    if (!use_bt) {
        #pragma unroll
        for (int t = 0; t < 8; t++) pf[t] = prow[lane + 32 * t];
    }

    cudaGridDependencySynchronize();   // predecessor's writes now visible

    {
        const float* BFin = use_bt ? BT : g_BF;
        const float4* bf4 = reinterpret_cast<const float4*>(BFin);
        float4* sbf4 = reinterpret_cast<float4*>(sBF);
        #pragma unroll
        for (int i = tid; i < N / 4; i += 256) sbf4[i] = bf4[i];
    }
    __syncthreads();

    float acc = 0.f;
    #pragma unroll
    for (int t = 0; t < 8; t++) {                 // prefetched half
        uint4 v = use_bt ? prow[lane + 32 * t] : pf[t];
        const float* b = &sBF[(lane + 32 * t) * 8];
        float2 f0 = __half22float2(*reinterpret_cast<__half2*>(&v.x));
        float2 f1 = __half22float2(*reinterpret_cast<__half2*>(&v.y));
        float2 f2 = __half22float2(*reinterpret_cast<__half2*>(&v.z));
        float2 f3 = __half22float2(*reinterpret_cast<__half2*>(&v.w));
        acc = fmaf(f0.x, b[0], acc);
        acc = fmaf(f0.y, b[1], acc);
        acc = fmaf(f1.x, b[2], acc);
        acc = fmaf(f1.y, b[3], acc);
        acc = fmaf(f2.x, b[4], acc);
        acc = fmaf(f2.y, b[5], acc);
        acc = fmaf(f3.x, b[6], acc);
        acc = fmaf(f3.y, b[7], acc);
    }
    #pragma unroll
    for (int t = 8; t < 16; t++) {                // streamed half
        uint4 v = prow[lane + 32 * t];
        const float* b = &sBF[(lane + 32 * t) * 8];
        float2 f0 = __half22float2(*reinterpret_cast<__half2*>(&v.x));
        float2 f1 = __half22float2(*reinterpret_cast<__half2*>(&v.y));
        float2 f2 = __half22float2(*reinterpret_cast<__half2*>(&v.z));
        float2 f3 = __half22float2(*reinterpret_cast<__half2*>(&v.w));
        acc = fmaf(f0.x, b[0], acc);
        acc = fmaf(f0.y, b[1], acc);
        acc = fmaf(f1.x, b[2], acc);
        acc = fmaf(f1.y, b[3], acc);
        acc = fmaf(f2.x, b[4], acc);
        acc = fmaf(f2.y, b[5], acc);
        acc = fmaf(f3.x, b[6], acc);
        acc = fmaf(f3.y, b[7], acc);
    }
    #pragma unroll
    for (int o = 16; o > 0; o >>= 1) acc += __shfl_xor_sync(0xFFFFFFFFu, acc, o);

    if (lane == 0) g_AF[row] = AT[row] / (1.0f + acc);
}

// ---------------------------------------------------------------------------
// Col matvec partial: tmp[cy][j] = sum_{i in chunk cy} AF[i] * Kh[i][j]
// grid = (16 col-tiles, 16 row-chunks) = 256 blocks.
// Prefetch first 4 Kh rows before gridsync (skip on iteration 0).
// ---------------------------------------------------------------------------
__global__ __launch_bounds__(256, 4)
void col_mv_partial_kernel(int first)
{
    __shared__ float sAF[CHUNK_ROWS];     // 1 KB
    __shared__ float sAcc[8 * COL_TILE];  // 8 KB

    const int tid     = threadIdx.x;
    const int warp    = tid >> 5;
    const int lane    = tid & 31;
    const int colBase = blockIdx.x * COL_TILE;
    const int rowBase = blockIdx.y * CHUNK_ROWS;

    const __half* Kbase = g_Kh;

    uint4 pf[4];
    if (!first) {
        #pragma unroll
        for (int s = 0; s < 4; s++) {
            const int r = warp + 8 * s;
            pf[s] = *reinterpret_cast<const uint4*>(
                Kbase + (((size_t)(rowBase + r)) << 12) + colBase + 8 * lane);
        }
    }

    cudaGridDependencySynchronize();   // AF (and on it=0, Kh) complete

    if (tid < CHUNK_ROWS) sAF[tid] = g_AF[rowBase + tid];
    __syncthreads();

    float acc[8];
    #pragma unroll
    for (int k = 0; k < 8; k++) acc[k] = 0.f;

    #pragma unroll 4
    for (int s = 0; s < CHUNK_ROWS / 8; s++) {    // 32 trips
        const int r = warp + 8 * s;
        const float a = sAF[r];
        uint4 v;
        if (s < 4 && !first) v = pf[s];
        else v = *reinterpret_cast<const uint4*>(
                 Kbase + (((size_t)(rowBase + r)) << 12) + colBase + 8 * lane);
        float2 f0 = __half22float2(*reinterpret_cast<__half2*>(&v.x));
        float2 f1 = __half22float2(*reinterpret_cast<__half2*>(&v.y));
        float2 f2 = __half22float2(*reinterpret_cast<__half2*>(&v.z));
        float2 f3 = __half22float2(*reinterpret_cast<__half2*>(&v.w));
        acc[0] = fmaf(a, f0.x, acc[0]);
        acc[1] = fmaf(a, f0.y, acc[1]);
        acc[2] = fmaf(a, f1.x, acc[2]);
        acc[3] = fmaf(a, f1.y, acc[3]);
        acc[4] = fmaf(a, f2.x, acc[4]);
        acc[5] = fmaf(a, f2.y, acc[5]);
        acc[6] = fmaf(a, f3.x, acc[6]);
        acc[7] = fmaf(a, f3.y, acc[7]);
    }

    #pragma unroll
    for (int k = 0; k < 8; k++) sAcc[warp * 256 + lane * 8 + k] = acc[k];
    __syncthreads();

    // Fixed-order cross-warp reduce; thread t owns column colBase + t.
    float s = 0.f;
    #pragma unroll
    for (int w = 0; w < 8; w++) s += sAcc[w * 256 + tid];
    __stcg(&g_tmp[blockIdx.y * N + colBase + tid], s);
}

// ---------------------------------------------------------------------------
// Finalize: BF[j] = BT[j] / (1 + sum_cy tmp[cy][j]).  grid = 16 x 256.
// ---------------------------------------------------------------------------
__global__ __launch_bounds__(256, 4)
void finalize_bf_kernel(const float* __restrict__ BT)
{
    cudaGridDependencySynchronize();   // all partials complete

    const int j = blockIdx.x * 256 + threadIdx.x;
    float s = 0.f;
    #pragma unroll
    for (int c = 0; c < ROW_CHUNKS; c++) s += __ldcg(&g_tmp[c * N + j]);
    g_BF[j] = BT[j] / (1.0f + s);
}

// ---------------------------------------------------------------------------
// Output: C[i][j] = param[i][j]^2 * AF[i] * BF[j]  — exact fp32 K.
// P prefetched before gridsync (input, immutable).
// ---------------------------------------------------------------------------
__global__ __launch_bounds__(256, 4)
void compute_c_kernel(const float* __restrict__ P, float* __restrict__ C)
{
    const size_t idx = (size_t)blockIdx.x * 256 + threadIdx.x;  // float4 index
    const float4 p = reinterpret_cast<const float4*>(P)[idx];

    cudaGridDependencySynchronize();   // final BF complete

    const int row  = (int)(idx >> 10);
    const int col4 = (int)(idx & 1023);
    const float a  = g_AF[row];
    const float4 b = *reinterpret_cast<const float4*>(&g_BF[col4 * 4]);

    float4 o;
    o.x = p.x * p.x * a * b.x;
    o.y = p.y * p.y * a * b.y;
    o.z = p.z * p.z * a * b.z;
    o.w = p.w * p.w * a * b.w;
    reinterpret_cast<float4*>(C)[idx] = o;
}

// ---------------------------------------------------------------------------
// PDL launch helper (PSS attribute). No explicit triggers anywhere: the
// implicit trigger at block completion preserves exact stream-order memory
// visibility. Capture-legal: kernel launches only.
// ---------------------------------------------------------------------------
template <typename K, typename... Args>
static inline void launch_pdl(K kernel, dim3 grid, dim3 block, Args... args)
{
    cudaLaunchConfig_t cfg = {};
    cfg.gridDim  = grid;
    cfg.blockDim = block;
    cudaLaunchAttribute attr[1];
    attr[0].id = cudaLaunchAttributeProgrammaticStreamSerialization;
    attr[0].val.programmaticStreamSerializationAllowed = 1;
    cfg.attrs    = attr;
    cfg.numAttrs = 1;
    cudaLaunchKernelEx(&cfg, kernel, args...);
}

// ---------------------------------------------------------------------------
// prep + 21 x {rowMV, colMV, finalize} + C = 65 graph nodes; boundaries
// hidden by PDL + prefetch-before-gridsync (immutable data only).
// No sync, no alloc, no memcpy, no fences, no atomics, no explicit triggers.
// ---------------------------------------------------------------------------
extern "C" void kernel_launch(void* const* d_in, const int* in_sizes, int n_in,
                              void* d_out, int out_size)
{
    const float* AT = (const float*)d_in[0];   // [4096]
    const float* BT = (const float*)d_in[1];   // [4096]
    const float* P  = (const float*)d_in[2];   // [4096, 4096]
    float* C = (float*)d_out;                  // [4096, 4096]

    launch_pdl(prep_kh_kernel, dim3((unsigned)(((size_t)N * N / 8) / 256)),
               dim3(256), P);

    const dim3 colGrid(16, ROW_CHUNKS);

    for (int it = 0; it < NITER; it++) {
        launch_pdl(row_mv_kernel, dim3(N / 8), dim3(256),
                   AT, BT, it == 0 ? 1 : 0);
        launch_pdl(col_mv_partial_kernel, colGrid, dim3(256),
                   it == 0 ? 1 : 0);
        launch_pdl(finalize_bf_kernel, dim3(N / 256), dim3(256), BT);
    }
    launch_pdl(compute_c_kernel,
               dim3((unsigned)(((size_t)N * (N / 4)) / 256)), dim3(256), P, C);
}